// round 8
// baseline (speedup 1.0000x reference)
#include <cuda_runtime.h>
#include <cstdint>

// Phase 1: bucket edges by dst (CAP per node), overflow -> spill list.
// Phase 2: warp-per-node gather-reduce, PLAIN st.v4 per output chunk
//          (every row written exactly once -> no output memset needed).
// Phase 3: 1-block overflow cleanup with red.add (normally zero work).

#define D_FEAT 64
#define CHUNKS 16
#define CAP 64            // Poisson(12.5): P(deg>64) ~ 1e-24 per node

#define MAX_NODES 131072
#define MAX_EDGES 2097152
#define MAX_OVF   4096

__device__ int g_cnt[MAX_NODES];
__device__ int g_elist[MAX_NODES * CAP];
__device__ int g_ovf_cnt;
__device__ int2 g_ovf[MAX_OVF];   // (src, dst)

// ---------------- build buckets ----------------

__global__ void bucket_kernel(const int* __restrict__ src,
                              const int* __restrict__ dst,
                              int n_edges, int n_nodes)
{
    int e = blockIdx.x * blockDim.x + threadIdx.x;
    if (e >= n_edges) return;
    int s = __ldg(src + e);
    int d = __ldg(dst + e);
    if ((unsigned)s >= (unsigned)n_nodes || (unsigned)d >= (unsigned)n_nodes) return;

    int pos = atomicAdd(&g_cnt[d], 1);
    if (pos < CAP) {
        g_elist[(size_t)d * CAP + pos] = s;
    } else {
        int op = atomicAdd(&g_ovf_cnt, 1);
        if (op < MAX_OVF) g_ovf[op] = make_int2(s, d);
    }
}

// ---------------- warp-per-node gather-reduce ----------------
// lane = 2 halves (edge-parallel) x 16 chunks; fold halves with 4 shfls;
// half 0 writes the row with a plain vector store (exactly-once coverage).

__global__ void aggregate_kernel(const float4* __restrict__ x4,
                                 float4* __restrict__ out4,
                                 int n_nodes)
{
    int warp = (blockIdx.x * blockDim.x + threadIdx.x) >> 5;
    if (warp >= n_nodes) return;
    int lane = threadIdx.x & 31;
    int chunk = lane & 15;
    int half = lane >> 4;

    int deg = g_cnt[warp];
    if (deg > CAP) deg = CAP;          // overflow edges handled by cleanup pass
    const int* bucket = g_elist + (size_t)warp * CAP;

    float4 a = make_float4(0.f, 0.f, 0.f, 0.f);
#pragma unroll 2
    for (int e = half; e < deg; e += 2) {
        int s = __ldg(bucket + e);
        float4 v = __ldg(x4 + (size_t)s * CHUNKS + chunk);
        a.x += v.x; a.y += v.y; a.z += v.z; a.w += v.w;
    }

    a.x += __shfl_down_sync(0xffffffffu, a.x, 16);
    a.y += __shfl_down_sync(0xffffffffu, a.y, 16);
    a.z += __shfl_down_sync(0xffffffffu, a.z, 16);
    a.w += __shfl_down_sync(0xffffffffu, a.w, 16);

    if (half == 0) {
        out4[(size_t)warp * CHUNKS + chunk] = a;
    }
}

// ---------------- overflow cleanup (runs AFTER aggregate) ----------------

__global__ void overflow_kernel(const float4* __restrict__ x4,
                                float* __restrict__ out)
{
    int n = g_ovf_cnt;
    if (n > MAX_OVF) n = MAX_OVF;
    for (int i = blockIdx.x * blockDim.x + threadIdx.x; i < n * CHUNKS;
         i += gridDim.x * blockDim.x) {
        int idx = i >> 4;
        int c = i & 15;
        int2 sd = g_ovf[idx];
        float4 v = __ldg(x4 + (size_t)sd.x * CHUNKS + c);
        float* dst_ptr = out + (size_t)sd.y * D_FEAT + (size_t)c * 4;
        asm volatile("red.global.add.v4.f32 [%0], {%1, %2, %3, %4};"
                     :: "l"(dst_ptr), "f"(v.x), "f"(v.y), "f"(v.z), "f"(v.w)
                     : "memory");
    }
}

// ---------------- fallback: proven atomic scatter (R4, 72us) ----------------

__global__ void scatter_add_kernel(const float4* __restrict__ x4,
                                   const int* __restrict__ src_idx,
                                   const int* __restrict__ dst_idx,
                                   float* __restrict__ out,
                                   int n_edges, int n_nodes)
{
    long long tid = (long long)blockIdx.x * blockDim.x + threadIdx.x;
    long long edge = tid >> 4;
    int chunk = (int)(tid & 15);
    if (edge >= n_edges) return;
    int s = __ldg(src_idx + edge);
    int d = __ldg(dst_idx + edge);
    if ((unsigned)s >= (unsigned)n_nodes || (unsigned)d >= (unsigned)n_nodes) return;
    float4 v = __ldg(x4 + (size_t)s * CHUNKS + chunk);
    float* dst_ptr = out + (size_t)d * D_FEAT + (size_t)chunk * 4;
    asm volatile("red.global.add.v4.f32 [%0], {%1, %2, %3, %4};"
                 :: "l"(dst_ptr), "f"(v.x), "f"(v.y), "f"(v.z), "f"(v.w)
                 : "memory");
}

extern "C" void kernel_launch(void* const* d_in, const int* in_sizes, int n_in,
                              void* d_out, int out_size)
{
    // Role detection by element count: x (6.4M fp32) > edge_index (2.5M int32)
    int xi = 0, ei = 1;
    if (n_in >= 2 && in_sizes[1] > in_sizes[0]) { xi = 1; ei = 0; }

    const float4* x4 = (const float4*)d_in[xi];
    const int* edge_index = (const int*)d_in[ei];

    int n_edges = in_sizes[ei] / 2;
    int n_nodes = in_sizes[xi] / D_FEAT;

    const int* src_idx = edge_index;            // row 0
    const int* dst_idx = edge_index + n_edges;  // row 1

    float* out = (float*)d_out;

    if (n_nodes > MAX_NODES || n_edges > MAX_EDGES) {
        cudaMemsetAsync(out, 0, (size_t)out_size * sizeof(float));
        long long total = (long long)n_edges * CHUNKS;
        scatter_add_kernel<<<(int)((total + 255) / 256), 256>>>(
            x4, src_idx, dst_idx, out, n_edges, n_nodes);
        return;
    }

    void* cnt_ptr = nullptr;
    cudaGetSymbolAddress(&cnt_ptr, g_cnt);
    void* ovf_ptr = nullptr;
    cudaGetSymbolAddress(&ovf_ptr, g_ovf_cnt);

    cudaMemsetAsync(cnt_ptr, 0, (size_t)n_nodes * sizeof(int));
    cudaMemsetAsync(ovf_ptr, 0, sizeof(int));

    bucket_kernel<<<(n_edges + 255) / 256, 256>>>(src_idx, dst_idx,
                                                  n_edges, n_nodes);

    long long total = (long long)n_nodes * 32;
    aggregate_kernel<<<(int)((total + 255) / 256), 256>>>(x4, (float4*)d_out,
                                                          n_nodes);

    overflow_kernel<<<1, 256>>>(x4, out);
}